// round 13
// baseline (speedup 1.0000x reference)
#include <cuda_runtime.h>
#include <cuda_bf16.h>

// Problem constants (fixed: P=64, K=8, C=512, N=3*P*K=1536)
#define NROWS 1536
#define CDIM  512
#define MCL   192
#define GK    8
#define MARGIN_KL 6.0f
#define MID_N 1024
#define MID_M 128
#define GBI   48
#define GBJ   3
#define KSPL  4                       // K splits of 128
#define NTILE (GBI * GBJ)             // 144 output tiles

// bf16 split planes: A-side [i][k] = {x_hi, x_lo, xs_hi, xs_lo}
__device__ __nv_bfloat16 g_A[4][NROWS * CDIM];
// B-side [j][k] = {hcen_hi, hcen_lo, logh_hi, logh_lo}
__device__ __nv_bfloat16 g_B[4][MCL * CDIM];
__device__ float g_rowc[NROWS];       // ent_x + lse
__device__ float g_enth[MCL];
__device__ float g_pd[KSPL * NROWS * MCL];   // K-split partial products
__device__ float g_part[NTILE * 4];
__device__ unsigned int g_tctr[NTILE];       // per-tile K-split counters
__device__ unsigned int g_ctr = 0;

// ---------------- bf16 split helpers ----------------
__device__ __forceinline__ unsigned int pkbf(float a, float b) {
    __nv_bfloat162 h = __floats2bfloat162_rn(a, b);   // low half = a
    return *reinterpret_cast<unsigned int*>(&h);
}
__device__ __forceinline__ float bfres(float v) {
    return v - __bfloat162float(__float2bfloat16_rn(v));
}

// ---------------- mma + ldmatrix ----------------
__device__ __forceinline__ void mma16816(float* d, const unsigned int* a,
                                         const unsigned int* b) {
    asm volatile(
        "mma.sync.aligned.m16n8k16.row.col.f32.bf16.bf16.f32 "
        "{%0,%1,%2,%3}, {%4,%5,%6,%7}, {%8,%9}, {%0,%1,%2,%3};"
        : "+f"(d[0]), "+f"(d[1]), "+f"(d[2]), "+f"(d[3])
        : "r"(a[0]), "r"(a[1]), "r"(a[2]), "r"(a[3]), "r"(b[0]), "r"(b[1]));
}
__device__ __forceinline__ void ldsm4(unsigned int* r, unsigned int saddr) {
    asm volatile(
        "ldmatrix.sync.aligned.m8n8.x4.shared.b16 {%0,%1,%2,%3}, [%4];"
        : "=r"(r[0]), "=r"(r[1]), "=r"(r[2]), "=r"(r[3]) : "r"(saddr));
}

// ---------------------------------------------------------------------------
// Kernel 1: softmax stats + centers; emits bf16 hi/lo planes. 192 x 256.
// (verified rounds 8-10)
// ---------------------------------------------------------------------------
__global__ void __launch_bounds__(256) k_stats(const float* __restrict__ x) {
    __shared__ float sxs[8][516];
    __shared__ float shc[512], slh[512];
    __shared__ float sred[8];
    const int j = blockIdx.x;
    const int t = threadIdx.x;
    const int w = t >> 5, lane = t & 31;
    const int row = j * GK + w;

    const float4* xr = reinterpret_cast<const float4*>(x + (size_t)row * CDIM);
    float4 v[4];
    #pragma unroll
    for (int q = 0; q < 4; q++) v[q] = xr[lane + 32 * q];

    float mx = -1e30f;
    #pragma unroll
    for (int q = 0; q < 4; q++)
        mx = fmaxf(mx, fmaxf(fmaxf(v[q].x, v[q].y), fmaxf(v[q].z, v[q].w)));
    #pragma unroll
    for (int o = 16; o; o >>= 1) mx = fmaxf(mx, __shfl_xor_sync(0xffffffffu, mx, o));

    float4 e[4];
    float s = 0.f;
    #pragma unroll
    for (int q = 0; q < 4; q++) {
        e[q].x = __expf(v[q].x - mx); e[q].y = __expf(v[q].y - mx);
        e[q].z = __expf(v[q].z - mx); e[q].w = __expf(v[q].w - mx);
        s += (e[q].x + e[q].y) + (e[q].z + e[q].w);
    }
    #pragma unroll
    for (int o = 16; o; o >>= 1) s += __shfl_xor_sync(0xffffffffu, s, o);

    const float lse = mx + __logf(s);
    const float inv = 1.0f / s;

    float* sx = &sxs[w][0];
    float ent = 0.f;
    #pragma unroll
    for (int q = 0; q < 4; q++) {
        float4 p = make_float4(e[q].x * inv, e[q].y * inv, e[q].z * inv, e[q].w * inv);
        reinterpret_cast<float4*>(sx)[lane + 32 * q] = p;
        const int kb = 4 * (lane + 32 * q);
        const size_t off = (size_t)row * CDIM + kb;
        *reinterpret_cast<uint2*>(&g_A[0][off]) =
            make_uint2(pkbf(v[q].x, v[q].y), pkbf(v[q].z, v[q].w));
        *reinterpret_cast<uint2*>(&g_A[1][off]) =
            make_uint2(pkbf(bfres(v[q].x), bfres(v[q].y)),
                       pkbf(bfres(v[q].z), bfres(v[q].w)));
        *reinterpret_cast<uint2*>(&g_A[2][off]) =
            make_uint2(pkbf(p.x, p.y), pkbf(p.z, p.w));
        *reinterpret_cast<uint2*>(&g_A[3][off]) =
            make_uint2(pkbf(bfres(p.x), bfres(p.y)),
                       pkbf(bfres(p.z), bfres(p.w)));
        ent += p.x * (v[q].x - lse) + p.y * (v[q].y - lse)
             + p.z * (v[q].z - lse) + p.w * (v[q].w - lse);
    }
    #pragma unroll
    for (int o = 16; o; o >>= 1) ent += __shfl_xor_sync(0xffffffffu, ent, o);
    if (lane == 0) g_rowc[row] = ent + lse;

    __syncthreads();

    float entp = 0.f;
    #pragma unroll
    for (int h = 0; h < 2; h++) {
        const int c = t + 256 * h;
        float hc = 0.f;
        #pragma unroll
        for (int r = 0; r < GK; r++) hc += sxs[r][c];
        hc *= (1.0f / (float)GK);
        const float l = __logf(fmaxf(hc, 1e-9f));
        shc[c] = hc;
        slh[c] = l;
        entp += hc * l;
    }
    #pragma unroll
    for (int o = 16; o; o >>= 1) entp += __shfl_xor_sync(0xffffffffu, entp, o);
    if (lane == 0) sred[w] = entp;
    __syncthreads();
    if (t == 0) {
        float eh = 0.f;
        #pragma unroll
        for (int r = 0; r < 8; r++) eh += sred[r];
        g_enth[j] = eh;
    }

    {
        const float h0 = shc[2 * t],  h1 = shc[2 * t + 1];
        const float l0 = slh[2 * t],  l1 = slh[2 * t + 1];
        const size_t off = (size_t)j * CDIM + 2 * t;
        *reinterpret_cast<unsigned int*>(&g_B[0][off]) = pkbf(h0, h1);
        *reinterpret_cast<unsigned int*>(&g_B[1][off]) = pkbf(bfres(h0), bfres(h1));
        *reinterpret_cast<unsigned int*>(&g_B[2][off]) = pkbf(l0, l1);
        *reinterpret_cast<unsigned int*>(&g_B[3][off]) = pkbf(bfres(l0), bfres(l1));
    }
}

// ---------------------------------------------------------------------------
// Kernel 2: bf16-split tensor GEMM, K-split across 4 independent CTAs/tile.
// Grid (48,3,4) = 576 CTAs x 256 threads (~4 CTAs/SM). CTA tile 32x64 over
// K=128. Last CTA per tile sums 4 partial planes + fused loss epilogue.
// ---------------------------------------------------------------------------
__global__ void __launch_bounds__(256, 4) k_mma(const long long* __restrict__ pids,
                                                float* __restrict__ out) {
    __shared__ __align__(16) __nv_bfloat16 sA[4][32][40];
    __shared__ __align__(16) __nv_bfloat16 sB[4][64][40];
    __shared__ float senth[64], srowc[32];
    __shared__ int sphc[64], spid[32];
    __shared__ float rp[8], rn[8];
    __shared__ int cp_[8], cn_[8];
    __shared__ bool slast_tile, slast_all;

    const int bi = blockIdx.x;     // 0..47
    const int bj = blockIdx.y;     // 0..2
    const int kh = blockIdx.z;     // 0..3 (K range kh*128..+127)
    const int t  = threadIdx.x;
    const int w  = t >> 5, lane = t & 31;
    const int g  = lane >> 2, t4 = lane & 3;
    const int wm = w >> 2;         // m-half (0/1): rows wm*16..+15
    const int wn = w & 3;          // n-quarter (0..3): cols wn*16..+15
    const int kbase_u4 = kh * 16;  // K base in uint4 (8 bf16) units

    float acc0[2][4], acc1[2][4];
    #pragma unroll
    for (int nt = 0; nt < 2; nt++)
        #pragma unroll
        for (int c = 0; c < 4; c++) { acc0[nt][c] = 0.f; acc1[nt][c] = 0.f; }

    // ldmatrix per-thread smem addresses (verified round 9)
    const int a_row = wm * 16 + (lane & 15);
    const int a_col8 = (lane >> 4) << 3;
    const int b_row = wn * 16 + (lane & 7) + ((lane & 16) ? 8 : 0);
    const int b_col8 = (lane & 8);
    unsigned int aaddr[4], baddr[4];
    #pragma unroll
    for (int arr = 0; arr < 4; arr++) {
        aaddr[arr] = (unsigned int)__cvta_generic_to_shared(&sA[arr][a_row][a_col8]);
        baddr[arr] = (unsigned int)__cvta_generic_to_shared(&sB[arr][b_row][b_col8]);
    }

    // loader mappings (uint4 = 8 bf16); 256 threads
    uint4 pa[2], pb[4];
    #pragma unroll
    for (int q = 0; q < 2; q++) {
        const int idx = t + 256 * q;
        const int arr = idx >> 7, rem = idx & 127;
        pa[q] = reinterpret_cast<const uint4*>(g_A[arr])
                    [(size_t)(bi * 32 + (rem >> 2)) * 64 + kbase_u4 + (rem & 3)];
    }
    #pragma unroll
    for (int q = 0; q < 4; q++) {
        const int idx = t + 256 * q;
        const int arr = idx >> 8, rem = idx & 255;
        pb[q] = reinterpret_cast<const uint4*>(g_B[arr])
                    [(size_t)(bj * 64 + (rem >> 2)) * 64 + kbase_u4 + (rem & 3)];
    }

    for (int ch = 0; ch < 4; ch++) {       // 4 chunks of 32 k
        #pragma unroll
        for (int q = 0; q < 2; q++) {
            const int idx = t + 256 * q;
            const int arr = idx >> 7, rem = idx & 127;
            *reinterpret_cast<uint4*>(&sA[arr][rem >> 2][(rem & 3) * 8]) = pa[q];
        }
        #pragma unroll
        for (int q = 0; q < 4; q++) {
            const int idx = t + 256 * q;
            const int arr = idx >> 8, rem = idx & 255;
            *reinterpret_cast<uint4*>(&sB[arr][rem >> 2][(rem & 3) * 8]) = pb[q];
        }
        __syncthreads();

        if (ch < 3) {
            const int ko = kbase_u4 + (ch + 1) * 4;
            #pragma unroll
            for (int q = 0; q < 2; q++) {
                const int idx = t + 256 * q;
                const int arr = idx >> 7, rem = idx & 127;
                pa[q] = reinterpret_cast<const uint4*>(g_A[arr])
                            [(size_t)(bi * 32 + (rem >> 2)) * 64 + ko + (rem & 3)];
            }
            #pragma unroll
            for (int q = 0; q < 4; q++) {
                const int idx = t + 256 * q;
                const int arr = idx >> 8, rem = idx & 255;
                pb[q] = reinterpret_cast<const uint4*>(g_B[arr])
                            [(size_t)(bj * 64 + (rem >> 2)) * 64 + ko + (rem & 3)];
            }
        }

        #pragma unroll
        for (int kk2 = 0; kk2 < 2; kk2++) {
            const unsigned int koff = kk2 * 32;

            unsigned int axh[4], axl[4], ash[4], asl[4];
            ldsm4(axh, aaddr[0] + koff);
            ldsm4(axl, aaddr[1] + koff);
            ldsm4(ash, aaddr[2] + koff);
            ldsm4(asl, aaddr[3] + koff);
            unsigned int bhh[4], bhl[4], blh[4], bll[4];
            ldsm4(bhh, baddr[0] + koff);
            ldsm4(bhl, baddr[1] + koff);
            ldsm4(blh, baddr[2] + koff);
            ldsm4(bll, baddr[3] + koff);

            mma16816(acc0[0], axh, bhh + 0);
            mma16816(acc0[1], axh, bhh + 2);
            mma16816(acc1[0], ash, blh + 0);
            mma16816(acc1[1], ash, blh + 2);
            mma16816(acc0[0], axh, bhl + 0);
            mma16816(acc0[1], axh, bhl + 2);
            mma16816(acc1[0], ash, bll + 0);
            mma16816(acc1[1], ash, bll + 2);
            mma16816(acc0[0], axl, bhh + 0);
            mma16816(acc0[1], axl, bhh + 2);
            mma16816(acc1[0], asl, blh + 0);
            mma16816(acc1[1], asl, blh + 2);
        }
        __syncthreads();
    }

    // ---- write K-split partial plane ----
    {
        float* pd = g_pd + (size_t)kh * (NROWS * MCL);
        #pragma unroll
        for (int nt = 0; nt < 2; nt++) {
            const int jl = wn * 16 + nt * 8 + 2 * t4;
            #pragma unroll
            for (int c = 0; c < 4; c++) {
                const int il = wm * 16 + g + (c >> 1) * 8;
                pd[(size_t)(bi * 32 + il) * MCL + bj * 64 + jl + (c & 1)] =
                    acc0[nt][c] + acc1[nt][c];
            }
        }
    }
    __threadfence();
    __syncthreads();

    const int tile = bi * GBJ + bj;
    if (t == 0) {
        slast_tile = (atomicAdd(&g_tctr[tile], 1u) == KSPL - 1);
    }
    __syncthreads();
    if (!slast_tile) return;

    // ---- last CTA of tile: sum 4 planes, classify, reduce ----
    __threadfence();
    if (t == 0) g_tctr[tile] = 0;   // reset for next graph replay

    if (t < 64) {
        senth[t] = g_enth[bj * 64 + t];
        sphc[t] = (int)pids[(size_t)(bj * 64 + t) * GK];
    } else if (t < 96) {
        const int r = t - 64;
        srowc[r] = g_rowc[bi * 32 + r];
        spid[r] = (int)pids[bi * 32 + r];
    }
    __syncthreads();

    float psum = 0.f, nsum = 0.f;
    int pcnt = 0, ncnt = 0;
    #pragma unroll
    for (int q = 0; q < 2; q++) {
        const int idx = t + 256 * q;          // 0..511 float4-groups
        const int r = idx >> 4;               // row in tile 0..31
        const int jf = (idx & 15) * 4;        // col 0..60
        const int i = bi * 32 + r;
        const size_t base = (size_t)i * MCL + bj * 64 + jf;
        const float4 p0 = *reinterpret_cast<const float4*>(g_pd + base);
        const float4 p1 = *reinterpret_cast<const float4*>(g_pd + (size_t)(NROWS * MCL) + base);
        const float4 p2 = *reinterpret_cast<const float4*>(g_pd + (size_t)(2 * NROWS * MCL) + base);
        const float4 p3 = *reinterpret_cast<const float4*>(g_pd + (size_t)(3 * NROWS * MCL) + base);
        const float rc = srowc[r];
        const int pi = spid[r];
        const bool itop = i < MID_N;
        const float dv[4] = {
            rc + senth[jf + 0] - ((p0.x + p1.x) + (p2.x + p3.x)),
            rc + senth[jf + 1] - ((p0.y + p1.y) + (p2.y + p3.y)),
            rc + senth[jf + 2] - ((p0.z + p1.z) + (p2.z + p3.z)),
            rc + senth[jf + 3] - ((p0.w + p1.w) + (p2.w + p3.w)) };
        #pragma unroll
        for (int c = 0; c < 4; c++) {
            const int jj = bj * 64 + jf + c;
            const bool mask = (pi == sphc[jf + c]);
            const bool region = itop != (jj < MID_M);
            if (mask) {
                if (region) { psum += dv[c]; pcnt++; }
            } else {
                nsum += fmaxf(MARGIN_KL - dv[c], 0.f);
                ncnt++;
            }
        }
    }

    #pragma unroll
    for (int o = 16; o; o >>= 1) {
        psum += __shfl_xor_sync(0xffffffffu, psum, o);
        nsum += __shfl_xor_sync(0xffffffffu, nsum, o);
        pcnt += __shfl_xor_sync(0xffffffffu, pcnt, o);
        ncnt += __shfl_xor_sync(0xffffffffu, ncnt, o);
    }
    if (lane == 0) { rp[w] = psum; rn[w] = nsum; cp_[w] = pcnt; cn_[w] = ncnt; }
    __syncthreads();
    if (t == 0) {
        float fp = 0.f, fn = 0.f; int ip = 0, in_ = 0;
        #pragma unroll
        for (int q = 0; q < 8; q++) { fp += rp[q]; fn += rn[q]; ip += cp_[q]; in_ += cn_[q]; }
        g_part[tile * 4 + 0] = fp;
        g_part[tile * 4 + 1] = fn;
        g_part[tile * 4 + 2] = (float)ip;
        g_part[tile * 4 + 3] = (float)in_;
        __threadfence();
        slast_all = (atomicAdd(&g_ctr, 1u) == NTILE - 1);
    }
    __syncthreads();

    if (slast_all) {
        __threadfence();
        float ps = 0.f, ns = 0.f, pc = 0.f, nc = 0.f;
        if (t < NTILE) {
            ps = g_part[t * 4 + 0];
            ns = g_part[t * 4 + 1];
            pc = g_part[t * 4 + 2];
            nc = g_part[t * 4 + 3];
        }
        #pragma unroll
        for (int o = 16; o; o >>= 1) {
            ps += __shfl_xor_sync(0xffffffffu, ps, o);
            ns += __shfl_xor_sync(0xffffffffu, ns, o);
            pc += __shfl_xor_sync(0xffffffffu, pc, o);
            nc += __shfl_xor_sync(0xffffffffu, nc, o);
        }
        if (lane == 0) { rp[w] = ps; rn[w] = ns; cp_[w] = (int)pc; cn_[w] = (int)nc; }
        __syncthreads();
        if (t == 0) {
            float fps = 0.f, fns = 0.f, fpc = 0.f, fnc = 0.f;
            #pragma unroll
            for (int q = 0; q < 8; q++) {
                fps += rp[q]; fns += rn[q];
                fpc += (float)cp_[q]; fnc += (float)cn_[q];
            }
            out[0] = fps / fmaxf(fpc, 1.0f) + fns / fmaxf(fnc, 1.0f);
            g_ctr = 0;   // reset for next graph replay
        }
    }
}

// ---------------------------------------------------------------------------
extern "C" void kernel_launch(void* const* d_in, const int* in_sizes, int n_in,
                              void* d_out, int out_size) {
    const float* x = (const float*)d_in[0];
    const long long* pids = (const long long*)d_in[1];
    (void)in_sizes; (void)n_in; (void)out_size;

    k_stats<<<MCL, 256>>>(x);
    dim3 gg(GBI, GBJ, KSPL);
    k_mma<<<gg, 256>>>(pids, (float*)d_out);
}

// round 14
// speedup vs baseline: 1.4844x; 1.4844x over previous
#include <cuda_runtime.h>
#include <cuda_bf16.h>
#include <cuda_fp16.h>

// Problem constants (fixed: P=64, K=8, C=512, N=3*P*K=1536)
#define NROWS 1536
#define CDIM  512
#define MCL   192
#define GK    8
#define MARGIN_KL 6.0f
#define MID_N 1024
#define MID_M 128
#define GBI   48
#define GBJ   3
#define NBLK  (GBI * GBJ)     // 144 mma blocks
#define SCALE 256.0f
#define INV_SCALE (1.0f / 256.0f)

// fp16 planes: A-side [i][k] = {x, 256*xs} ; B-side [j][k] = {256*hcen, logh}
__device__ __half g_A[2][NROWS * CDIM];
__device__ __half g_B[2][MCL * CDIM];
__device__ float g_rowc[NROWS];     // ent_x + lse
__device__ float g_enth[MCL];
__device__ float g_part[NBLK * 4];
__device__ unsigned int g_ctr = 0;

// ---------------- fp16 pack helper ----------------
__device__ __forceinline__ unsigned int pkh(float a, float b) {
    __half2 h = __floats2half2_rn(a, b);   // low half = a
    return *reinterpret_cast<unsigned int*>(&h);
}

// ---------------- mma + ldmatrix ----------------
__device__ __forceinline__ void mma16816h(float* d, const unsigned int* a,
                                          const unsigned int* b) {
    asm volatile(
        "mma.sync.aligned.m16n8k16.row.col.f32.f16.f16.f32 "
        "{%0,%1,%2,%3}, {%4,%5,%6,%7}, {%8,%9}, {%0,%1,%2,%3};"
        : "+f"(d[0]), "+f"(d[1]), "+f"(d[2]), "+f"(d[3])
        : "r"(a[0]), "r"(a[1]), "r"(a[2]), "r"(a[3]), "r"(b[0]), "r"(b[1]));
}
__device__ __forceinline__ void ldsm4(unsigned int* r, unsigned int saddr) {
    asm volatile(
        "ldmatrix.sync.aligned.m8n8.x4.shared.b16 {%0,%1,%2,%3}, [%4];"
        : "=r"(r[0]), "=r"(r[1]), "=r"(r[2]), "=r"(r[3]) : "r"(saddr));
}

// ---------------------------------------------------------------------------
// Kernel 1: softmax stats + centers; emits fp16 planes. 192 x 256.
// Warp w handles row 8*j + w. (structure verified rounds 8-13)
// ---------------------------------------------------------------------------
__global__ void __launch_bounds__(256) k_stats(const float* __restrict__ x) {
    __shared__ float sxs[8][516];
    __shared__ float shc[512], slh[512];
    __shared__ float sred[8];
    const int j = blockIdx.x;
    const int t = threadIdx.x;
    const int w = t >> 5, lane = t & 31;
    const int row = j * GK + w;

    const float4* xr = reinterpret_cast<const float4*>(x + (size_t)row * CDIM);
    float4 v[4];
    #pragma unroll
    for (int q = 0; q < 4; q++) v[q] = xr[lane + 32 * q];

    float mx = -1e30f;
    #pragma unroll
    for (int q = 0; q < 4; q++)
        mx = fmaxf(mx, fmaxf(fmaxf(v[q].x, v[q].y), fmaxf(v[q].z, v[q].w)));
    #pragma unroll
    for (int o = 16; o; o >>= 1) mx = fmaxf(mx, __shfl_xor_sync(0xffffffffu, mx, o));

    float4 e[4];
    float s = 0.f;
    #pragma unroll
    for (int q = 0; q < 4; q++) {
        e[q].x = __expf(v[q].x - mx); e[q].y = __expf(v[q].y - mx);
        e[q].z = __expf(v[q].z - mx); e[q].w = __expf(v[q].w - mx);
        s += (e[q].x + e[q].y) + (e[q].z + e[q].w);
    }
    #pragma unroll
    for (int o = 16; o; o >>= 1) s += __shfl_xor_sync(0xffffffffu, s, o);

    const float lse = mx + __logf(s);
    const float inv = 1.0f / s;

    float* sx = &sxs[w][0];
    float ent = 0.f;
    #pragma unroll
    for (int q = 0; q < 4; q++) {
        float4 p = make_float4(e[q].x * inv, e[q].y * inv, e[q].z * inv, e[q].w * inv);
        reinterpret_cast<float4*>(sx)[lane + 32 * q] = p;
        const int kb = 4 * (lane + 32 * q);
        const size_t off = (size_t)row * CDIM + kb;
        // x plane (fp16)
        *reinterpret_cast<uint2*>(&g_A[0][off]) =
            make_uint2(pkh(v[q].x, v[q].y), pkh(v[q].z, v[q].w));
        // 256*xs plane (fp16; scaled to stay in normal range)
        *reinterpret_cast<uint2*>(&g_A[1][off]) =
            make_uint2(pkh(SCALE * p.x, SCALE * p.y), pkh(SCALE * p.z, SCALE * p.w));
        ent += p.x * (v[q].x - lse) + p.y * (v[q].y - lse)
             + p.z * (v[q].z - lse) + p.w * (v[q].w - lse);
    }
    #pragma unroll
    for (int o = 16; o; o >>= 1) ent += __shfl_xor_sync(0xffffffffu, ent, o);
    if (lane == 0) g_rowc[row] = ent + lse;

    __syncthreads();

    float entp = 0.f;
    #pragma unroll
    for (int h = 0; h < 2; h++) {
        const int c = t + 256 * h;
        float hc = 0.f;
        #pragma unroll
        for (int r = 0; r < GK; r++) hc += sxs[r][c];
        hc *= (1.0f / (float)GK);
        const float l = __logf(fmaxf(hc, 1e-9f));
        shc[c] = hc;
        slh[c] = l;
        entp += hc * l;
    }
    #pragma unroll
    for (int o = 16; o; o >>= 1) entp += __shfl_xor_sync(0xffffffffu, entp, o);
    if (lane == 0) sred[w] = entp;
    __syncthreads();
    if (t == 0) {
        float eh = 0.f;
        #pragma unroll
        for (int r = 0; r < 8; r++) eh += sred[r];
        g_enth[j] = eh;
    }

    // fp16 B planes: thread t covers cols {2t, 2t+1}
    {
        const float h0 = shc[2 * t],  h1 = shc[2 * t + 1];
        const float l0 = slh[2 * t],  l1 = slh[2 * t + 1];
        const size_t off = (size_t)j * CDIM + 2 * t;
        *reinterpret_cast<unsigned int*>(&g_B[0][off]) = pkh(SCALE * h0, SCALE * h1);
        *reinterpret_cast<unsigned int*>(&g_B[1][off]) = pkh(l0, l1);
    }
}

// ---------------------------------------------------------------------------
// Kernel 2: fp16 1-term tensor GEMM + fused loss epilogue.
// Grid (48,3) = 144 CTAs x 256 threads (8 warps). CTA tile 32x64; warp 16x16.
// acc = x.(256 hcen) + (256 xs).logh ; dist = rowc + enth - acc/256.
// Per k16 per warp: 4 ldsm + 4 mma (was 8+12 in round 9).
// ---------------------------------------------------------------------------
__global__ void __launch_bounds__(256) k_mma(const long long* __restrict__ pids,
                                             float* __restrict__ out) {
    __shared__ __align__(16) __half sA[2][32][40];
    __shared__ __align__(16) __half sB[2][64][40];
    __shared__ float senth[MCL], srowc[32];
    __shared__ int sphc[MCL], spid[32];
    __shared__ float rp[8], rn[8];
    __shared__ int cp_[8], cn_[8];
    __shared__ bool slast;

    const int bi = blockIdx.x;     // 0..47
    const int bj = blockIdx.y;     // 0..2
    const int t  = threadIdx.x;
    const int w  = t >> 5, lane = t & 31;
    const int g  = lane >> 2, t4 = lane & 3;
    const int wm = w >> 2;         // m-half (0/1): rows wm*16..+15
    const int wn = w & 3;          // n-quarter (0..3): cols wn*16..+15

    float acc[2][4];
    #pragma unroll
    for (int nt = 0; nt < 2; nt++)
        #pragma unroll
        for (int c = 0; c < 4; c++) acc[nt][c] = 0.f;

    // ldmatrix per-thread smem addresses (maps verified rounds 9/13)
    const int a_row = wm * 16 + (lane & 15);
    const int a_col8 = (lane >> 4) << 3;
    const int b_row = wn * 16 + (lane & 7) + ((lane & 16) ? 8 : 0);
    const int b_col8 = (lane & 8);
    unsigned int aaddr[2], baddr[2];
    #pragma unroll
    for (int arr = 0; arr < 2; arr++) {
        aaddr[arr] = (unsigned int)__cvta_generic_to_shared(&sA[arr][a_row][a_col8]);
        baddr[arr] = (unsigned int)__cvta_generic_to_shared(&sB[arr][b_row][b_col8]);
    }

    // loader mappings (uint4 = 8 fp16); rows are 64 uint4 wide (512 halves)
    // A: 2 planes x 32 rows x 4 uint4/chunk = 256 -> 1/thread
    // B: 2 planes x 64 rows x 4 uint4/chunk = 512 -> 2/thread
    uint4 pa, pb[2];
    {
        const int arr = t >> 7, rem = t & 127;
        pa = reinterpret_cast<const uint4*>(g_A[arr])
                 [(size_t)(bi * 32 + (rem >> 2)) * 64 + (rem & 3)];
    }
    #pragma unroll
    for (int q = 0; q < 2; q++) {
        const int idx = t + 256 * q;
        const int arr = idx >> 8, rem = idx & 255;
        pb[q] = reinterpret_cast<const uint4*>(g_B[arr])
                    [(size_t)(bj * 64 + (rem >> 2)) * 64 + (rem & 3)];
    }

    for (int ch = 0; ch < 16; ch++) {      // chunks of 32 k
        {
            const int arr = t >> 7, rem = t & 127;
            *reinterpret_cast<uint4*>(&sA[arr][rem >> 2][(rem & 3) * 8]) = pa;
        }
        #pragma unroll
        for (int q = 0; q < 2; q++) {
            const int idx = t + 256 * q;
            const int arr = idx >> 8, rem = idx & 255;
            *reinterpret_cast<uint4*>(&sB[arr][rem >> 2][(rem & 3) * 8]) = pb[q];
        }
        __syncthreads();

        if (ch < 15) {
            const int ko = (ch + 1) * 4;
            {
                const int arr = t >> 7, rem = t & 127;
                pa = reinterpret_cast<const uint4*>(g_A[arr])
                         [(size_t)(bi * 32 + (rem >> 2)) * 64 + ko + (rem & 3)];
            }
            #pragma unroll
            for (int q = 0; q < 2; q++) {
                const int idx = t + 256 * q;
                const int arr = idx >> 8, rem = idx & 255;
                pb[q] = reinterpret_cast<const uint4*>(g_B[arr])
                            [(size_t)(bj * 64 + (rem >> 2)) * 64 + ko + (rem & 3)];
            }
        }

        #pragma unroll
        for (int kk2 = 0; kk2 < 2; kk2++) {
            const unsigned int koff = kk2 * 32;   // 16 fp16 = 32 bytes

            unsigned int ax[4], as_[4];
            ldsm4(ax, aaddr[0] + koff);
            ldsm4(as_, aaddr[1] + koff);
            unsigned int bh[4], bl[4];            // {b0_nt0,b1_nt0,b0_nt1,b1_nt1}
            ldsm4(bh, baddr[0] + koff);
            ldsm4(bl, baddr[1] + koff);

            mma16816h(acc[0], ax, bh + 0);
            mma16816h(acc[1], ax, bh + 2);
            mma16816h(acc[0], as_, bl + 0);
            mma16816h(acc[1], as_, bl + 2);
        }
        __syncthreads();
    }

    // ---- fused epilogue ----
    if (t < MCL) {
        senth[t] = g_enth[t];
        sphc[t] = (int)pids[(size_t)t * GK];
    }
    if (t >= 192 && t < 224) {
        const int r = t - 192;
        srowc[r] = g_rowc[bi * 32 + r];
        spid[r] = (int)pids[bi * 32 + r];
    }
    __syncthreads();

    float psum = 0.f, nsum = 0.f;
    int pcnt = 0, ncnt = 0;
    #pragma unroll
    for (int nt = 0; nt < 2; nt++) {
        const int jl = wn * 16 + nt * 8 + 2 * t4;
        const int jg = bj * 64 + jl;
        #pragma unroll
        for (int c = 0; c < 4; c++) {
            const int il = wm * 16 + g + (c >> 1) * 8;
            const int jj = jg + (c & 1);
            const int i = bi * 32 + il;
            const float dist = srowc[il] + senth[jj] - acc[nt][c] * INV_SCALE;
            const bool mask = (spid[il] == sphc[jj]);
            const bool region = (i < MID_N) != (jj < MID_M);
            if (mask) {
                if (region) { psum += dist; pcnt++; }
            } else {
                nsum += fmaxf(MARGIN_KL - dist, 0.f);
                ncnt++;
            }
        }
    }

    #pragma unroll
    for (int o = 16; o; o >>= 1) {
        psum += __shfl_xor_sync(0xffffffffu, psum, o);
        nsum += __shfl_xor_sync(0xffffffffu, nsum, o);
        pcnt += __shfl_xor_sync(0xffffffffu, pcnt, o);
        ncnt += __shfl_xor_sync(0xffffffffu, ncnt, o);
    }
    if (lane == 0) { rp[w] = psum; rn[w] = nsum; cp_[w] = pcnt; cn_[w] = ncnt; }
    __syncthreads();
    const int blk = bi * GBJ + bj;
    if (t == 0) {
        float fp = 0.f, fn = 0.f; int ip = 0, in_ = 0;
        #pragma unroll
        for (int q = 0; q < 8; q++) { fp += rp[q]; fn += rn[q]; ip += cp_[q]; in_ += cn_[q]; }
        g_part[blk * 4 + 0] = fp;
        g_part[blk * 4 + 1] = fn;
        g_part[blk * 4 + 2] = (float)ip;
        g_part[blk * 4 + 3] = (float)in_;
        __threadfence();
        slast = (atomicAdd(&g_ctr, 1u) == NBLK - 1);
    }
    __syncthreads();

    if (slast) {
        __threadfence();
        float ps = 0.f, ns = 0.f, pc = 0.f, nc = 0.f;
        if (t < NBLK) {
            ps = g_part[t * 4 + 0];
            ns = g_part[t * 4 + 1];
            pc = g_part[t * 4 + 2];
            nc = g_part[t * 4 + 3];
        }
        #pragma unroll
        for (int o = 16; o; o >>= 1) {
            ps += __shfl_xor_sync(0xffffffffu, ps, o);
            ns += __shfl_xor_sync(0xffffffffu, ns, o);
            pc += __shfl_xor_sync(0xffffffffu, pc, o);
            nc += __shfl_xor_sync(0xffffffffu, nc, o);
        }
        if (lane == 0) { rp[w] = ps; rn[w] = ns; cp_[w] = (int)pc; cn_[w] = (int)nc; }
        __syncthreads();
        if (t == 0) {
            float fps = 0.f, fns = 0.f, fpc = 0.f, fnc = 0.f;
            #pragma unroll
            for (int q = 0; q < 8; q++) {
                fps += rp[q]; fns += rn[q];
                fpc += (float)cp_[q]; fnc += (float)cn_[q];
            }
            out[0] = fps / fmaxf(fpc, 1.0f) + fns / fmaxf(fnc, 1.0f);
            g_ctr = 0;   // reset for next graph replay
        }
    }
}

// ---------------------------------------------------------------------------
extern "C" void kernel_launch(void* const* d_in, const int* in_sizes, int n_in,
                              void* d_out, int out_size) {
    const float* x = (const float*)d_in[0];
    const long long* pids = (const long long*)d_in[1];
    (void)in_sizes; (void)n_in; (void)out_size;

    k_stats<<<MCL, 256>>>(x);
    dim3 gg(GBI, GBJ);
    k_mma<<<gg, 256>>>(pids, (float*)d_out);
}

// round 16
// speedup vs baseline: 1.5886x; 1.0702x over previous
#include <cuda_runtime.h>
#include <cuda_bf16.h>
#include <cuda_fp16.h>

// Problem constants (fixed: P=64, K=8, C=512, N=3*P*K=1536)
#define NROWS 1536
#define CDIM  512
#define MCL   192
#define GK    8
#define MARGIN_KL 6.0f
#define MID_N 1024
#define MID_M 128
#define GBI   48
#define GBJ   3
#define NBLK  (GBI * GBJ)     // 144 mma blocks
#define SCALE 256.0f
#define INV_SCALE (1.0f / 256.0f)
#define NCH   16              // chunks of 32 k
#define STAGE_BYTES 12288     // A 2x2048 + B 2x4096
#define BOFF  4096

// fp16 planes: A-side [i][k] = {x, 256*xs} ; B-side [j][k] = {256*hcen, logh}
__device__ __half g_A[2][NROWS * CDIM];
__device__ __half g_B[2][MCL * CDIM];
__device__ float g_rowc[NROWS];     // ent_x + lse
__device__ float g_enth[MCL];
__device__ float g_part[NBLK * 4];
__device__ unsigned int g_ctr = 0;

// ---------------- fp16 pack helper ----------------
__device__ __forceinline__ unsigned int pkh(float a, float b) {
    __half2 h = __floats2half2_rn(a, b);   // low half = a
    return *reinterpret_cast<unsigned int*>(&h);
}

// ---------------- mma / ldmatrix / cp.async ----------------
__device__ __forceinline__ void mma16816h(float* d, const unsigned int* a,
                                          const unsigned int* b) {
    asm volatile(
        "mma.sync.aligned.m16n8k16.row.col.f32.f16.f16.f32 "
        "{%0,%1,%2,%3}, {%4,%5,%6,%7}, {%8,%9}, {%0,%1,%2,%3};"
        : "+f"(d[0]), "+f"(d[1]), "+f"(d[2]), "+f"(d[3])
        : "r"(a[0]), "r"(a[1]), "r"(a[2]), "r"(a[3]), "r"(b[0]), "r"(b[1]));
}
__device__ __forceinline__ void ldsm4(unsigned int* r, unsigned int saddr) {
    asm volatile(
        "ldmatrix.sync.aligned.m8n8.x4.shared.b16 {%0,%1,%2,%3}, [%4];"
        : "=r"(r[0]), "=r"(r[1]), "=r"(r[2]), "=r"(r[3]) : "r"(saddr));
}
__device__ __forceinline__ void cpa16(unsigned int dst, const void* src) {
    asm volatile("cp.async.cg.shared.global [%0], [%1], 16;" :: "r"(dst), "l"(src));
}
__device__ __forceinline__ void cpa_commit() { asm volatile("cp.async.commit_group;"); }
__device__ __forceinline__ void cpa_wait1() { asm volatile("cp.async.wait_group 1;"); }

// ---------------------------------------------------------------------------
// Kernel 1: softmax stats + centers; emits fp16 planes. 192 x 256.
// (verified round 14)
// ---------------------------------------------------------------------------
__global__ void __launch_bounds__(256) k_stats(const float* __restrict__ x) {
    __shared__ float sxs[8][516];
    __shared__ float shc[512], slh[512];
    __shared__ float sred[8];
    const int j = blockIdx.x;
    const int t = threadIdx.x;
    const int w = t >> 5, lane = t & 31;
    const int row = j * GK + w;

    const float4* xr = reinterpret_cast<const float4*>(x + (size_t)row * CDIM);
    float4 v[4];
    #pragma unroll
    for (int q = 0; q < 4; q++) v[q] = xr[lane + 32 * q];

    float mx = -1e30f;
    #pragma unroll
    for (int q = 0; q < 4; q++)
        mx = fmaxf(mx, fmaxf(fmaxf(v[q].x, v[q].y), fmaxf(v[q].z, v[q].w)));
    #pragma unroll
    for (int o = 16; o; o >>= 1) mx = fmaxf(mx, __shfl_xor_sync(0xffffffffu, mx, o));

    float4 e[4];
    float s = 0.f;
    #pragma unroll
    for (int q = 0; q < 4; q++) {
        e[q].x = __expf(v[q].x - mx); e[q].y = __expf(v[q].y - mx);
        e[q].z = __expf(v[q].z - mx); e[q].w = __expf(v[q].w - mx);
        s += (e[q].x + e[q].y) + (e[q].z + e[q].w);
    }
    #pragma unroll
    for (int o = 16; o; o >>= 1) s += __shfl_xor_sync(0xffffffffu, s, o);

    const float lse = mx + __logf(s);
    const float inv = 1.0f / s;

    float* sx = &sxs[w][0];
    float ent = 0.f;
    #pragma unroll
    for (int q = 0; q < 4; q++) {
        float4 p = make_float4(e[q].x * inv, e[q].y * inv, e[q].z * inv, e[q].w * inv);
        reinterpret_cast<float4*>(sx)[lane + 32 * q] = p;
        const int kb = 4 * (lane + 32 * q);
        const size_t off = (size_t)row * CDIM + kb;
        *reinterpret_cast<uint2*>(&g_A[0][off]) =
            make_uint2(pkh(v[q].x, v[q].y), pkh(v[q].z, v[q].w));
        *reinterpret_cast<uint2*>(&g_A[1][off]) =
            make_uint2(pkh(SCALE * p.x, SCALE * p.y), pkh(SCALE * p.z, SCALE * p.w));
        ent += p.x * (v[q].x - lse) + p.y * (v[q].y - lse)
             + p.z * (v[q].z - lse) + p.w * (v[q].w - lse);
    }
    #pragma unroll
    for (int o = 16; o; o >>= 1) ent += __shfl_xor_sync(0xffffffffu, ent, o);
    if (lane == 0) g_rowc[row] = ent + lse;

    __syncthreads();

    float entp = 0.f;
    #pragma unroll
    for (int h = 0; h < 2; h++) {
        const int c = t + 256 * h;
        float hc = 0.f;
        #pragma unroll
        for (int r = 0; r < GK; r++) hc += sxs[r][c];
        hc *= (1.0f / (float)GK);
        const float l = __logf(fmaxf(hc, 1e-9f));
        shc[c] = hc;
        slh[c] = l;
        entp += hc * l;
    }
    #pragma unroll
    for (int o = 16; o; o >>= 1) entp += __shfl_xor_sync(0xffffffffu, entp, o);
    if (lane == 0) sred[w] = entp;
    __syncthreads();
    if (t == 0) {
        float eh = 0.f;
        #pragma unroll
        for (int r = 0; r < 8; r++) eh += sred[r];
        g_enth[j] = eh;
    }

    {
        const float h0 = shc[2 * t],  h1 = shc[2 * t + 1];
        const float l0 = slh[2 * t],  l1 = slh[2 * t + 1];
        const size_t off = (size_t)j * CDIM + 2 * t;
        *reinterpret_cast<unsigned int*>(&g_B[0][off]) = pkh(SCALE * h0, SCALE * h1);
        *reinterpret_cast<unsigned int*>(&g_B[1][off]) = pkh(l0, l1);
    }
}

// ---------------------------------------------------------------------------
// Kernel 2: fp16 1-term tensor GEMM, cp.async 3-stage ring.
// Fixed sync: wait_group 1 -> __syncthreads -> issue -> compute, so ALL
// threads' chunk-ch copies are visible before any ldsm reads the stage.
// Grid (48,3) = 144 CTAs x 256 threads; CTA tile 32x64; warp tile 16x16.
// ---------------------------------------------------------------------------
__global__ void __launch_bounds__(256) k_mma(const long long* __restrict__ pids,
                                             float* __restrict__ out) {
    __shared__ __align__(128) char arena[3 * STAGE_BYTES];   // 36864 B
    __shared__ float senth[MCL], srowc[32];
    __shared__ int sphc[MCL], spid[32];
    __shared__ float rp[8], rn[8];
    __shared__ int cp_[8], cn_[8];
    __shared__ bool slast;

    const int bi = blockIdx.x;     // 0..47
    const int bj = blockIdx.y;     // 0..2
    const int t  = threadIdx.x;
    const int w  = t >> 5, lane = t & 31;
    const int g  = lane >> 2, t4 = lane & 3;
    const int wm = w >> 2;         // m-half (0/1)
    const int wn = w & 3;          // n-quarter (0..3)

    const unsigned int arena_u32 = (unsigned int)__cvta_generic_to_shared(arena);

    float acc[2][4];
    #pragma unroll
    for (int nt = 0; nt < 2; nt++)
        #pragma unroll
        for (int c = 0; c < 4; c++) acc[nt][c] = 0.f;

    // ---- loader maps (16B cp.async per transfer) ----
    // A: 2 planes x 32 rows x 4 c8 = 256 transfers -> 1/thread
    const int pA = t >> 7, remA = t & 127;
    const int rowA = remA >> 2, c8A = remA & 3;
    const unsigned int dstA = pA * 2048 + c8A * 512 + (rowA >> 3) * 128 + (rowA & 7) * 16;
    const __half* srcA0 = g_A[pA] + (size_t)(bi * 32 + rowA) * CDIM + c8A * 8;
    // B: 2 planes x 64 rows x 4 c8 = 512 transfers -> 2/thread
    int pB[2], rowB[2], c8B[2];
    unsigned int dstB[2];
    const __half* srcB0[2];
    #pragma unroll
    for (int q = 0; q < 2; q++) {
        const int idx = t + 256 * q;
        pB[q] = idx >> 8;
        const int rem = idx & 255;
        rowB[q] = rem >> 2; c8B[q] = rem & 3;
        dstB[q] = BOFF + pB[q] * 4096 + c8B[q] * 1024
                + (rowB[q] >> 3) * 128 + (rowB[q] & 7) * 16;
        srcB0[q] = g_B[pB[q]] + (size_t)(bj * 64 + rowB[q]) * CDIM + c8B[q] * 8;
    }

    // ---- ldmatrix lane offsets (tile-contiguous; layout verified round 10) ----
    const int tmA = 2 * wm + ((lane >> 3) & 1);
    const int tkA = lane >> 4;
    const unsigned int aoff = tkA * 512 + tmA * 128 + (lane & 7) * 16;
    const int tnB = 2 * wn + (lane >> 4);
    const int tkB = (lane >> 3) & 1;
    const unsigned int boff = BOFF + tkB * 1024 + tnB * 128 + (lane & 7) * 16;

    // ---- prologue: stage chunks 0 and 1 (groups g0, g1) ----
    #pragma unroll
    for (int pc = 0; pc < 2; pc++) {
        const unsigned int sb = arena_u32 + pc * STAGE_BYTES;
        cpa16(sb + dstA, srcA0 + pc * 32);
        cpa16(sb + dstB[0], srcB0[0] + pc * 32);
        cpa16(sb + dstB[1], srcB0[1] + pc * 32);
        cpa_commit();
    }

    int st = 0;
    for (int ch = 0; ch < NCH; ch++) {
        cpa_wait1();       // this thread's chunk-ch group (g_ch) complete
        __syncthreads();   // ALL threads' chunk-ch data landed; compute(ch-1)
                           // done -> stage (ch+2)%3 free for refill
        if (ch + 2 < NCH) {
            const int st2 = (st + 2 >= 3) ? st - 1 : st + 2;
            const unsigned int sb = arena_u32 + st2 * STAGE_BYTES;
            const int ko = (ch + 2) * 32;
            cpa16(sb + dstA, srcA0 + ko);
            cpa16(sb + dstB[0], srcB0[0] + ko);
            cpa16(sb + dstB[1], srcB0[1] + ko);
        }
        cpa_commit();      // always commit (possibly empty group): g_{ch+2}

        const unsigned int sb = arena_u32 + st * STAGE_BYTES;
        #pragma unroll
        for (int kk2 = 0; kk2 < 2; kk2++) {
            unsigned int ax[4], as_[4];
            ldsm4(ax, sb + aoff + kk2 * 1024 + 0 * 2048);
            ldsm4(as_, sb + aoff + kk2 * 1024 + 1 * 2048);
            unsigned int bh[4], bl[4];   // {b0_nt0,b1_nt0,b0_nt1,b1_nt1}
            ldsm4(bh, sb + boff + kk2 * 2048 + 0 * 4096);
            ldsm4(bl, sb + boff + kk2 * 2048 + 1 * 4096);

            mma16816h(acc[0], ax, bh + 0);
            mma16816h(acc[1], ax, bh + 2);
            mma16816h(acc[0], as_, bl + 0);
            mma16816h(acc[1], as_, bl + 2);
        }
        st = (st + 1 >= 3) ? 0 : st + 1;
    }
    __syncthreads();

    // ---- fused epilogue (verified round 14) ----
    if (t < MCL) {
        senth[t] = g_enth[t];
        sphc[t] = (int)pids[(size_t)t * GK];
    }
    if (t >= 192 && t < 224) {
        const int r = t - 192;
        srowc[r] = g_rowc[bi * 32 + r];
        spid[r] = (int)pids[bi * 32 + r];
    }
    __syncthreads();

    float psum = 0.f, nsum = 0.f;
    int pcnt = 0, ncnt = 0;
    #pragma unroll
    for (int nt = 0; nt < 2; nt++) {
        const int jl = wn * 16 + nt * 8 + 2 * t4;
        const int jg = bj * 64 + jl;
        #pragma unroll
        for (int c = 0; c < 4; c++) {
            const int il = wm * 16 + g + (c >> 1) * 8;
            const int jj = jg + (c & 1);
            const int i = bi * 32 + il;
            const float dist = srowc[il] + senth[jj] - acc[nt][c] * INV_SCALE;
            const bool mask = (spid[il] == sphc[jj]);
            const bool region = (i < MID_N) != (jj < MID_M);
            if (mask) {
                if (region) { psum += dist; pcnt++; }
            } else {
                nsum += fmaxf(MARGIN_KL - dist, 0.f);
                ncnt++;
            }
        }
    }

    #pragma unroll
    for (int o = 16; o; o >>= 1) {
        psum += __shfl_xor_sync(0xffffffffu, psum, o);
        nsum += __shfl_xor_sync(0xffffffffu, nsum, o);
        pcnt += __shfl_xor_sync(0xffffffffu, pcnt, o);
        ncnt += __shfl_xor_sync(0xffffffffu, ncnt, o);
    }
    if (lane == 0) { rp[w] = psum; rn[w] = nsum; cp_[w] = pcnt; cn_[w] = ncnt; }
    __syncthreads();
    const int blk = bi * GBJ + bj;
    if (t == 0) {
        float fp = 0.f, fn = 0.f; int ip = 0, in_ = 0;
        #pragma unroll
        for (int q = 0; q < 8; q++) { fp += rp[q]; fn += rn[q]; ip += cp_[q]; in_ += cn_[q]; }
        g_part[blk * 4 + 0] = fp;
        g_part[blk * 4 + 1] = fn;
        g_part[blk * 4 + 2] = (float)ip;
        g_part[blk * 4 + 3] = (float)in_;
        __threadfence();
        slast = (atomicAdd(&g_ctr, 1u) == NBLK - 1);
    }
    __syncthreads();

    if (slast) {
        __threadfence();
        float ps = 0.f, ns = 0.f, pc = 0.f, nc = 0.f;
        if (t < NBLK) {
            ps = g_part[t * 4 + 0];
            ns = g_part[t * 4 + 1];
            pc = g_part[t * 4 + 2];
            nc = g_part[t * 4 + 3];
        }
        #pragma unroll
        for (int o = 16; o; o >>= 1) {
            ps += __shfl_xor_sync(0xffffffffu, ps, o);
            ns += __shfl_xor_sync(0xffffffffu, ns, o);
            pc += __shfl_xor_sync(0xffffffffu, pc, o);
            nc += __shfl_xor_sync(0xffffffffu, nc, o);
        }
        if (lane == 0) { rp[w] = ps; rn[w] = ns; cp_[w] = (int)pc; cn_[w] = (int)nc; }
        __syncthreads();
        if (t == 0) {
            float fps = 0.f, fns = 0.f, fpc = 0.f, fnc = 0.f;
            #pragma unroll
            for (int q = 0; q < 8; q++) {
                fps += rp[q]; fns += rn[q];
                fpc += (float)cp_[q]; fnc += (float)cn_[q];
            }
            out[0] = fps / fmaxf(fpc, 1.0f) + fns / fmaxf(fnc, 1.0f);
            g_ctr = 0;   // reset for next graph replay
        }
    }
}

// ---------------------------------------------------------------------------
extern "C" void kernel_launch(void* const* d_in, const int* in_sizes, int n_in,
                              void* d_out, int out_size) {
    const float* x = (const float*)d_in[0];
    const long long* pids = (const long long*)d_in[1];
    (void)in_sizes; (void)n_in; (void)out_size;

    k_stats<<<MCL, 256>>>(x);
    dim3 gg(GBI, GBJ);
    k_mma<<<gg, 256>>>(pids, (float*)d_out);
}